// round 1
// baseline (speedup 1.0000x reference)
#include <cuda_runtime.h>

// MultiScaleTrendLoss: loss = mean_{b,t,c} sum_i w_i * ema(pred-target, a_i)[b,t,c]^2
// pred/target: (64, 4096, 64) fp32, contiguous. Output: 1 fp32 scalar.

#define BB 64
#define TT 4096
#define CC 64
#define CHUNK 256
#define NCHUNK (TT / CHUNK)      // 16
#define WARM 128
#define NWARPS (BB * NCHUNK)     // 1024

__device__ float g_partials[NWARPS];

#define A0 0.1f
#define A1 0.3f
#define A2 0.5f
#define W0 0.5f
#define W1 0.3f
#define W2 0.2f

__global__ __launch_bounds__(256) void ema_loss_kernel(
    const float* __restrict__ pred, const float* __restrict__ targ)
{
    const int gw   = (blockIdx.x * blockDim.x + threadIdx.x) >> 5; // warp id: 0..1023
    const int lane = threadIdx.x & 31;
    const int b     = gw >> 4;             // / NCHUNK
    const int chunk = gw & (NCHUNK - 1);
    const int t0 = chunk * CHUNK;
    const int ts = (chunk == 0) ? 0 : (t0 - WARM);

    const float2* __restrict__ p2 = reinterpret_cast<const float2*>(pred);
    const float2* __restrict__ q2 = reinterpret_cast<const float2*>(targ);

    // index in float2 units; row stride along t is CC/2 = 32 float2
    int idx = (b * TT + ts) * (CC / 2) + lane;

    // init at t = ts: y = x_ts for all alphas
    float2 pv = p2[idx];
    float2 qv = q2[idx];
    float dx = pv.x - qv.x;
    float dy = pv.y - qv.y;
    float e0x = dx, e0y = dy;
    float e1x = dx, e1y = dy;
    float e2x = dx, e2y = dy;
    float a0 = 0.f, a1 = 0.f, a2 = 0.f;
    if (chunk == 0) {
        // t = 0 is a real output sample (y0 = x0)
        float s = dx * dx + dy * dy;
        a0 = s; a1 = s; a2 = s;
    }

    // warmup (no accumulation): t = ts+1 .. t0-1  (127 steps, only chunk > 0)
    const int nwarm = (chunk == 0) ? 0 : (WARM - 1);
    #pragma unroll 8
    for (int k = 0; k < nwarm; ++k) {
        idx += CC / 2;
        pv = p2[idx]; qv = q2[idx];
        dx = pv.x - qv.x; dy = pv.y - qv.y;
        e0x = fmaf(A0, dx - e0x, e0x);  e0y = fmaf(A0, dy - e0y, e0y);
        e1x = fmaf(A1, dx - e1x, e1x);  e1y = fmaf(A1, dy - e1y, e1y);
        e2x = fmaf(A2, dx - e2x, e2x);  e2y = fmaf(A2, dy - e2y, e2y);
    }

    // main (accumulate): 255 steps for chunk 0 (t=1..255), 256 otherwise
    const int nmain = (chunk == 0) ? (CHUNK - 1) : CHUNK;
    #pragma unroll 8
    for (int k = 0; k < nmain; ++k) {
        idx += CC / 2;
        pv = p2[idx]; qv = q2[idx];
        dx = pv.x - qv.x; dy = pv.y - qv.y;
        e0x = fmaf(A0, dx - e0x, e0x);  e0y = fmaf(A0, dy - e0y, e0y);
        e1x = fmaf(A1, dx - e1x, e1x);  e1y = fmaf(A1, dy - e1y, e1y);
        e2x = fmaf(A2, dx - e2x, e2x);  e2y = fmaf(A2, dy - e2y, e2y);
        a0 = fmaf(e0x, e0x, a0);  a0 = fmaf(e0y, e0y, a0);
        a1 = fmaf(e1x, e1x, a1);  a1 = fmaf(e1y, e1y, a1);
        a2 = fmaf(e2x, e2x, a2);  a2 = fmaf(e2y, e2y, a2);
    }

    float v = W0 * a0 + W1 * a1 + W2 * a2;
    #pragma unroll
    for (int off = 16; off; off >>= 1)
        v += __shfl_xor_sync(0xffffffffu, v, off);
    if (lane == 0) g_partials[gw] = v;
}

__global__ __launch_bounds__(NWARPS) void reduce_kernel(float* __restrict__ out)
{
    __shared__ float s[32];
    const int tid = threadIdx.x;
    float v = g_partials[tid];
    #pragma unroll
    for (int off = 16; off; off >>= 1)
        v += __shfl_xor_sync(0xffffffffu, v, off);
    if ((tid & 31) == 0) s[tid >> 5] = v;
    __syncthreads();
    if (tid < 32) {
        float w = s[tid];
        #pragma unroll
        for (int off = 16; off; off >>= 1)
            w += __shfl_xor_sync(0xffffffffu, w, off);
        if (tid == 0)
            out[0] = w * (1.0f / ((float)BB * (float)TT * (float)CC));
    }
}

extern "C" void kernel_launch(void* const* d_in, const int* in_sizes, int n_in,
                              void* d_out, int out_size)
{
    const float* pred = (const float*)d_in[0];
    const float* targ = (const float*)d_in[1];
    float* out = (float*)d_out;
    (void)in_sizes; (void)n_in; (void)out_size;

    // 1024 warps, 256 threads/block -> 128 blocks (single wave on 148 SMs)
    ema_loss_kernel<<<(NWARPS * 32) / 256, 256>>>(pred, targ);
    reduce_kernel<<<1, NWARPS>>>(out);
}

// round 2
// speedup vs baseline: 1.7223x; 1.7223x over previous
#include <cuda_runtime.h>

// MultiScaleTrendLoss: loss = mean_{b,t,c} sum_i w_i * ema(pred-target, a_i)[b,t,c]^2
// pred/target: (64, 4096, 64) fp32. EMA linearity: ema(p)-ema(t) = ema(p-t).
// T split into chunks of 128 with 128-row warmup (truncation ~1.4e-6 rel).

#define BB 64
#define TT 4096
#define CC 64
#define CHUNK 128
#define NCHUNK (TT / CHUNK)        // 32
#define WARM 128
#define NWARPS (BB * NCHUNK)       // 2048
#define THREADS 128
#define BLOCKS (NWARPS * 32 / THREADS)  // 512

#define A0 0.1f
#define A1 0.3f
#define A2 0.5f
#define W0 0.5f
#define W1 0.3f
#define W2 0.2f

__device__ float g_partials[NWARPS];
__device__ unsigned int g_count = 0;

__global__ __launch_bounds__(THREADS) void ema_loss_kernel(
    const float* __restrict__ pred, const float* __restrict__ targ,
    float* __restrict__ out)
{
    const int gw   = (blockIdx.x * blockDim.x + threadIdx.x) >> 5; // 0..2047
    const int lane = threadIdx.x & 31;
    const int b     = gw >> 5;              // / NCHUNK
    const int chunk = gw & (NCHUNK - 1);
    const int t0 = chunk * CHUNK;
    const int ts = (chunk == 0) ? 0 : (t0 - WARM);
    const int rows    = (chunk == 0) ? CHUNK : (CHUNK + WARM); // 128 or 256
    const int accFrom = (chunk == 0) ? 1 : WARM;               // accumulate for k >= accFrom

    // base pointers: row stride along t is CC/2 = 32 float2
    const float2* __restrict__ p2 = reinterpret_cast<const float2*>(pred)
                                    + (b * TT + ts) * (CC / 2) + lane;
    const float2* __restrict__ q2 = reinterpret_cast<const float2*>(targ)
                                    + (b * TT + ts) * (CC / 2) + lane;

    // ---- 4-deep register prefetch pipeline ----
    constexpr int P = 4;
    float2 bp[P], bq[P];
    #pragma unroll
    for (int i = 0; i < P; ++i) {
        bp[i] = p2[i * (CC / 2)];
        bq[i] = q2[i * (CC / 2)];
    }

    // k = 0: EMA init y0 = x0
    float dx = bp[0].x - bq[0].x;
    float dy = bp[0].y - bq[0].y;
    float e0x = dx, e0y = dy;
    float e1x = dx, e1y = dy;
    float e2x = dx, e2y = dy;
    float a0 = 0.f, a1 = 0.f, a2 = 0.f;
    if (chunk == 0) {           // t=0 is a real output sample
        float s = dx * dx + dy * dy;
        a0 = s; a1 = s; a2 = s;
    }
    // refill slot 0 with row P
    bp[0] = p2[P * (CC / 2)];
    bq[0] = q2[P * (CC / 2)];

    #pragma unroll 4
    for (int k = 1; k < rows; ++k) {
        const int slot = k & (P - 1);
        dx = bp[slot].x - bq[slot].x;
        dy = bp[slot].y - bq[slot].y;
        // prefetch row k+P into the slot just consumed
        if (k + P < rows) {
            bp[slot] = p2[(k + P) * (CC / 2)];
            bq[slot] = q2[(k + P) * (CC / 2)];
        }
        e0x = fmaf(A0, dx - e0x, e0x);  e0y = fmaf(A0, dy - e0y, e0y);
        e1x = fmaf(A1, dx - e1x, e1x);  e1y = fmaf(A1, dy - e1y, e1y);
        e2x = fmaf(A2, dx - e2x, e2x);  e2y = fmaf(A2, dy - e2y, e2y);
        if (k >= accFrom) {
            a0 = fmaf(e0x, e0x, a0);  a0 = fmaf(e0y, e0y, a0);
            a1 = fmaf(e1x, e1x, a1);  a1 = fmaf(e1y, e1y, a1);
            a2 = fmaf(e2x, e2x, a2);  a2 = fmaf(e2y, e2y, a2);
        }
    }

    float v = W0 * a0 + W1 * a1 + W2 * a2;
    #pragma unroll
    for (int off = 16; off; off >>= 1)
        v += __shfl_xor_sync(0xffffffffu, v, off);
    if (lane == 0) g_partials[gw] = v;

    // ---- fused deterministic final reduction (last-block ticket) ----
    __threadfence();
    __syncthreads();
    __shared__ unsigned int s_isLast;
    if (threadIdx.x == 0) {
        unsigned int t = atomicAdd(&g_count, 1u);
        s_isLast = (t == (unsigned int)(gridDim.x - 1));
    }
    __syncthreads();
    if (s_isLast) {
        float s = 0.f;
        #pragma unroll
        for (int i = threadIdx.x; i < NWARPS; i += THREADS)
            s += g_partials[i];
        #pragma unroll
        for (int off = 16; off; off >>= 1)
            s += __shfl_xor_sync(0xffffffffu, s, off);
        __shared__ float sm[THREADS / 32];
        if ((threadIdx.x & 31) == 0) sm[threadIdx.x >> 5] = s;
        __syncthreads();
        if (threadIdx.x == 0) {
            float tot = 0.f;
            #pragma unroll
            for (int i = 0; i < THREADS / 32; ++i) tot += sm[i];
            out[0] = tot * (1.0f / ((float)BB * (float)TT * (float)CC));
            g_count = 0;   // reset for next graph replay
        }
    }
}

extern "C" void kernel_launch(void* const* d_in, const int* in_sizes, int n_in,
                              void* d_out, int out_size)
{
    const float* pred = (const float*)d_in[0];
    const float* targ = (const float*)d_in[1];
    float* out = (float*)d_out;
    (void)in_sizes; (void)n_in; (void)out_size;

    ema_loss_kernel<<<BLOCKS, THREADS>>>(pred, targ, out);
}

// round 3
// speedup vs baseline: 2.6461x; 1.5364x over previous
#include <cuda_runtime.h>

// MultiScaleTrendLoss: loss = mean_{b,t,c} sum_i w_i * ema(pred-target, a_i)[b,t,c]^2
// Exact chunked EMA: y_k = z_k + beta^{k+1} * C  (z = zero-init local EMA, C = carry).
// Phase 1: per-chunk A=sum z^2, S=sum beta^{k+1} z, E=z_end (reads data ONCE).
// Phase 2: sequential carry scan over 64 chunks + loss assembly (9MB, L2-resident).

#define BB 64
#define TT 4096
#define CC 64
#define CHUNK 64
#define NCHUNK (TT / CHUNK)          // 64
#define NWARPS (BB * NCHUNK)         // 4096
#define THREADS 256
#define BLOCKS (NWARPS * 32 / THREADS)  // 512
#define SEG (BB * NCHUNK * 32)       // 131072 floats per (alpha,comp) plane

#define AL0 0.1f
#define AL1 0.3f
#define AL2 0.5f
#define BE0 0.9f
#define BE1 0.7f
#define BE2 0.5f

constexpr double dpow(double b, int n) { double r = 1.0; for (int i = 0; i < n; ++i) r *= b; return r; }
constexpr double gsum(double beta, int L) { double q = beta * beta; return q * (1.0 - dpow(q, L)) / (1.0 - q); }

__device__ const float c_BL[3] = { (float)dpow(0.9, CHUNK), (float)dpow(0.7, CHUNK), (float)dpow(0.5, CHUNK) };
__device__ const float c_G[3]  = { (float)gsum(0.9, CHUNK), (float)gsum(0.7, CHUNK), (float)gsum(0.5, CHUNK) };
__device__ const float c_W[3]  = { 0.5f, 0.3f, 0.2f };

__device__ float g_A[3 * 2 * SEG];
__device__ float g_S[3 * 2 * SEG];
__device__ float g_E[3 * 2 * SEG];
__device__ float g_D0[2 * BB * 32];
__device__ float g_p2[48];
__device__ unsigned int g_count2 = 0;

__global__ __launch_bounds__(THREADS) void ema_phase1(
    const float* __restrict__ pred, const float* __restrict__ targ)
{
    const int gw   = (blockIdx.x * blockDim.x + threadIdx.x) >> 5; // 0..4095
    const int lane = threadIdx.x & 31;
    const int b     = gw >> 6;               // / NCHUNK
    const int chunk = gw & (NCHUNK - 1);

    const float2* __restrict__ p2 = reinterpret_cast<const float2*>(pred)
                                    + (b * TT + chunk * CHUNK) * (CC / 2) + lane;
    const float2* __restrict__ q2 = reinterpret_cast<const float2*>(targ)
                                    + (b * TT + chunk * CHUNK) * (CC / 2) + lane;

    constexpr int P = 4;
    float2 bp[P], bq[P];
    #pragma unroll
    for (int i = 0; i < P; ++i) { bp[i] = p2[i * (CC / 2)]; bq[i] = q2[i * (CC / 2)]; }

    // zero-init local EMA states, sum-of-squares, weighted sums
    float z0x = 0.f, z0y = 0.f, z1x = 0.f, z1y = 0.f, z2x = 0.f, z2y = 0.f;
    float A0x = 0.f, A0y = 0.f, A1x = 0.f, A1y = 0.f, A2x = 0.f, A2y = 0.f;
    float S0x = 0.f, S0y = 0.f, S1x = 0.f, S1y = 0.f, S2x = 0.f, S2y = 0.f;
    float pw0 = BE0, pw1 = BE1, pw2 = BE2;   // beta^{k+1}

    const float d0x = bp[0].x - bq[0].x;     // row-0 diff (chunk 0's virtual carry)
    const float d0y = bp[0].y - bq[0].y;

    auto step = [&](float dx, float dy) {
        z0x = fmaf(AL0, dx - z0x, z0x);  z0y = fmaf(AL0, dy - z0y, z0y);
        z1x = fmaf(AL1, dx - z1x, z1x);  z1y = fmaf(AL1, dy - z1y, z1y);
        z2x = fmaf(AL2, dx - z2x, z2x);  z2y = fmaf(AL2, dy - z2y, z2y);
        A0x = fmaf(z0x, z0x, A0x);  A0y = fmaf(z0y, z0y, A0y);
        A1x = fmaf(z1x, z1x, A1x);  A1y = fmaf(z1y, z1y, A1y);
        A2x = fmaf(z2x, z2x, A2x);  A2y = fmaf(z2y, z2y, A2y);
        S0x = fmaf(pw0, z0x, S0x);  S0y = fmaf(pw0, z0y, S0y);
        S1x = fmaf(pw1, z1x, S1x);  S1y = fmaf(pw1, z1y, S1y);
        S2x = fmaf(pw2, z2x, S2x);  S2y = fmaf(pw2, z2y, S2y);
        pw0 *= BE0; pw1 *= BE1; pw2 *= BE2;
    };

    #pragma unroll 8
    for (int k = 0; k < CHUNK - P; ++k) {
        const int slot = k & (P - 1);
        const float dx = bp[slot].x - bq[slot].x;
        const float dy = bp[slot].y - bq[slot].y;
        bp[slot] = p2[(k + P) * (CC / 2)];
        bq[slot] = q2[(k + P) * (CC / 2)];
        step(dx, dy);
    }
    #pragma unroll
    for (int k = CHUNK - P; k < CHUNK; ++k) {
        const int slot = k & (P - 1);
        step(bp[slot].x - bq[slot].x, bp[slot].y - bq[slot].y);
    }

    // store intermediates: layout [alpha][comp][b][chunk][lane]
    const int base = (b * NCHUNK + chunk) * 32 + lane;
    g_A[0 * SEG + base] = A0x;  g_A[1 * SEG + base] = A0y;
    g_A[2 * SEG + base] = A1x;  g_A[3 * SEG + base] = A1y;
    g_A[4 * SEG + base] = A2x;  g_A[5 * SEG + base] = A2y;
    g_S[0 * SEG + base] = S0x;  g_S[1 * SEG + base] = S0y;
    g_S[2 * SEG + base] = S1x;  g_S[3 * SEG + base] = S1y;
    g_S[4 * SEG + base] = S2x;  g_S[5 * SEG + base] = S2y;
    g_E[0 * SEG + base] = z0x;  g_E[1 * SEG + base] = z0y;
    g_E[2 * SEG + base] = z1x;  g_E[3 * SEG + base] = z1y;
    g_E[4 * SEG + base] = z2x;  g_E[5 * SEG + base] = z2y;
    if (chunk == 0) {
        g_D0[0 * BB * 32 + b * 32 + lane] = d0x;
        g_D0[1 * BB * 32 + b * 32 + lane] = d0y;
    }
}

__global__ __launch_bounds__(256) void ema_phase2(float* __restrict__ out)
{
    const int t    = blockIdx.x * 256 + threadIdx.x;  // 0..12287
    const int lane = t & 31;
    const int b    = (t >> 5) & (BB - 1);
    const int comp = (t >> 11) & 1;
    const int a    = t >> 12;                          // 0..2

    const float bl = c_BL[a];
    const float G  = c_G[a];
    const float Wt = c_W[a];

    float C = g_D0[comp * BB * 32 + b * 32 + lane];    // virtual carry for chunk 0
    const int i0 = (a * 2 + comp) * SEG + b * NCHUNK * 32 + lane;

    float loss = 0.f;
    #pragma unroll 8
    for (int c = 0; c < NCHUNK; ++c) {
        const int i = i0 + c * 32;
        const float Av = g_A[i];
        const float Sv = g_S[i];
        const float Ev = g_E[i];
        loss += Av + 2.f * C * Sv + C * C * G;
        C = fmaf(bl, C, Ev);
    }
    float v = Wt * loss;

    #pragma unroll
    for (int off = 16; off; off >>= 1)
        v += __shfl_xor_sync(0xffffffffu, v, off);
    __shared__ float sm[8];
    if (lane == 0) sm[threadIdx.x >> 5] = v;
    __syncthreads();
    if (threadIdx.x == 0) {
        float s = 0.f;
        #pragma unroll
        for (int i = 0; i < 8; ++i) s += sm[i];
        g_p2[blockIdx.x] = s;
    }

    // deterministic last-block final reduce
    __threadfence();
    __syncthreads();
    __shared__ unsigned int s_isLast;
    if (threadIdx.x == 0) {
        unsigned int tk = atomicAdd(&g_count2, 1u);
        s_isLast = (tk == (unsigned int)(gridDim.x - 1));
    }
    __syncthreads();
    if (s_isLast) {
        float w = (threadIdx.x < 48) ? g_p2[threadIdx.x] : 0.f;
        #pragma unroll
        for (int off = 16; off; off >>= 1)
            w += __shfl_xor_sync(0xffffffffu, w, off);
        __shared__ float sm2[8];
        if ((threadIdx.x & 31) == 0) sm2[threadIdx.x >> 5] = w;
        __syncthreads();
        if (threadIdx.x == 0) {
            float tot = 0.f;
            #pragma unroll
            for (int i = 0; i < 8; ++i) tot += sm2[i];
            out[0] = tot * (1.0f / ((float)BB * (float)TT * (float)CC));
            g_count2 = 0;   // reset for next graph replay
        }
    }
}

extern "C" void kernel_launch(void* const* d_in, const int* in_sizes, int n_in,
                              void* d_out, int out_size)
{
    const float* pred = (const float*)d_in[0];
    const float* targ = (const float*)d_in[1];
    float* out = (float*)d_out;
    (void)in_sizes; (void)n_in; (void)out_size;

    ema_phase1<<<BLOCKS, THREADS>>>(pred, targ);
    ema_phase2<<<48, 256>>>(out);
}

// round 6
// speedup vs baseline: 2.6759x; 1.0113x over previous
#include <cuda_runtime.h>

// MultiScaleTrendLoss: loss = mean_{b,t,c} sum_i w_i * ema(pred-target, a_i)[b,t,c]^2
// Exact chunked EMA: y_k = z_k + beta^{k+1} * C. Phase1 reads data once (at HBM
// roofline). Carry scan decomposed hierarchically: 64 chunks -> 4 segments of 16;
// each segment reduces to loss = P + Q*C + R*C^2 with affine carry-out.

#define BB 64
#define TT 4096
#define CC 64
#define CHUNK 64
#define NCHUNK (TT / CHUNK)             // 64
#define NWARPS (BB * NCHUNK)            // 4096
#define THREADS 256
#define BLOCKS (NWARPS * 32 / THREADS)  // 512
#define SEG (BB * NCHUNK * 32)          // 131072 floats per (alpha,comp) plane
#define NCHAIN (3 * 2 * BB * 32)        // 12288 chains
#define NSEGS 4
#define SEGLEN (NCHUNK / NSEGS)         // 16

#define AL0 0.1f
#define AL1 0.3f
#define AL2 0.5f
#define BE0 0.9f
#define BE1 0.7f
#define BE2 0.5f

__host__ __device__ constexpr double dpow(double b, int n) {
    double r = 1.0; for (int i = 0; i < n; ++i) r *= b; return r;
}
// sum_{k=1..L} beta^{2k}
__host__ __device__ constexpr double gsum(double beta, int L) {
    double q = beta * beta; return q * (1.0 - dpow(q, L)) / (1.0 - q);
}
// sum_{k=0..n-1} x^k
__host__ __device__ constexpr double geo0(double x, int n) {
    double s = 0.0, p = 1.0; for (int k = 0; k < n; ++k) { s += p; p *= x; } return s;
}

// per-alpha compile-time constants (selected in-kernel; fold to immediates)
__device__ __forceinline__ float pick3(int a, float x0, float x1, float x2) {
    return (a == 0) ? x0 : ((a == 1) ? x1 : x2);
}
#define BL_F(a)  pick3(a, (float)dpow(0.9, CHUNK), (float)dpow(0.7, CHUNK), (float)dpow(0.5, CHUNK))
#define G_F(a)   pick3(a, (float)gsum(0.9, CHUNK), (float)gsum(0.7, CHUNK), (float)gsum(0.5, CHUNK))
#define R_F(a)   pick3(a, (float)(gsum(0.9, CHUNK) * geo0(dpow(0.9, 2 * CHUNK), SEGLEN)), \
                          (float)(gsum(0.7, CHUNK) * geo0(dpow(0.7, 2 * CHUNK), SEGLEN)), \
                          (float)(gsum(0.5, CHUNK) * geo0(dpow(0.5, 2 * CHUNK), SEGLEN)))
#define M16_F(a) pick3(a, (float)dpow(0.9, CHUNK * SEGLEN), \
                          (float)dpow(0.7, CHUNK * SEGLEN), \
                          (float)dpow(0.5, CHUNK * SEGLEN))
#define W_F(a)   pick3(a, 0.5f, 0.3f, 0.2f)

__device__ float g_A[3 * 2 * SEG];
__device__ float g_S[3 * 2 * SEG];
__device__ float g_E[3 * 2 * SEG];
__device__ float g_D0[2 * BB * 32];
__device__ float g_P[NSEGS * NCHAIN];
__device__ float g_Q[NSEGS * NCHAIN];
__device__ float g_L[NSEGS * NCHAIN];
__device__ float g_p2[48];
__device__ unsigned int g_count2 = 0;

// ---------------- Phase 1: stream data once, emit per-chunk A/S/E ----------------
__global__ __launch_bounds__(THREADS) void ema_phase1(
    const float* __restrict__ pred, const float* __restrict__ targ)
{
    const int gw   = (blockIdx.x * blockDim.x + threadIdx.x) >> 5;
    const int lane = threadIdx.x & 31;
    const int b     = gw >> 6;
    const int chunk = gw & (NCHUNK - 1);

    const float2* __restrict__ p2 = reinterpret_cast<const float2*>(pred)
                                    + (b * TT + chunk * CHUNK) * (CC / 2) + lane;
    const float2* __restrict__ q2 = reinterpret_cast<const float2*>(targ)
                                    + (b * TT + chunk * CHUNK) * (CC / 2) + lane;

    constexpr int P = 4;
    float2 bp[P], bq[P];
    #pragma unroll
    for (int i = 0; i < P; ++i) { bp[i] = p2[i * (CC / 2)]; bq[i] = q2[i * (CC / 2)]; }

    float z0x = 0.f, z0y = 0.f, z1x = 0.f, z1y = 0.f, z2x = 0.f, z2y = 0.f;
    float A0x = 0.f, A0y = 0.f, A1x = 0.f, A1y = 0.f, A2x = 0.f, A2y = 0.f;
    float S0x = 0.f, S0y = 0.f, S1x = 0.f, S1y = 0.f, S2x = 0.f, S2y = 0.f;
    float pw0 = BE0, pw1 = BE1, pw2 = BE2;

    const float d0x = bp[0].x - bq[0].x;
    const float d0y = bp[0].y - bq[0].y;

    auto step = [&](float dx, float dy) {
        z0x = fmaf(AL0, dx - z0x, z0x);  z0y = fmaf(AL0, dy - z0y, z0y);
        z1x = fmaf(AL1, dx - z1x, z1x);  z1y = fmaf(AL1, dy - z1y, z1y);
        z2x = fmaf(AL2, dx - z2x, z2x);  z2y = fmaf(AL2, dy - z2y, z2y);
        A0x = fmaf(z0x, z0x, A0x);  A0y = fmaf(z0y, z0y, A0y);
        A1x = fmaf(z1x, z1x, A1x);  A1y = fmaf(z1y, z1y, A1y);
        A2x = fmaf(z2x, z2x, A2x);  A2y = fmaf(z2y, z2y, A2y);
        S0x = fmaf(pw0, z0x, S0x);  S0y = fmaf(pw0, z0y, S0y);
        S1x = fmaf(pw1, z1x, S1x);  S1y = fmaf(pw1, z1y, S1y);
        S2x = fmaf(pw2, z2x, S2x);  S2y = fmaf(pw2, z2y, S2y);
        pw0 *= BE0; pw1 *= BE1; pw2 *= BE2;
    };

    #pragma unroll 8
    for (int k = 0; k < CHUNK - P; ++k) {
        const int slot = k & (P - 1);
        const float dx = bp[slot].x - bq[slot].x;
        const float dy = bp[slot].y - bq[slot].y;
        bp[slot] = p2[(k + P) * (CC / 2)];
        bq[slot] = q2[(k + P) * (CC / 2)];
        step(dx, dy);
    }
    #pragma unroll
    for (int k = CHUNK - P; k < CHUNK; ++k) {
        const int slot = k & (P - 1);
        step(bp[slot].x - bq[slot].x, bp[slot].y - bq[slot].y);
    }

    const int base = (b * NCHUNK + chunk) * 32 + lane;
    g_A[0 * SEG + base] = A0x;  g_A[1 * SEG + base] = A0y;
    g_A[2 * SEG + base] = A1x;  g_A[3 * SEG + base] = A1y;
    g_A[4 * SEG + base] = A2x;  g_A[5 * SEG + base] = A2y;
    g_S[0 * SEG + base] = S0x;  g_S[1 * SEG + base] = S0y;
    g_S[2 * SEG + base] = S1x;  g_S[3 * SEG + base] = S1y;
    g_S[4 * SEG + base] = S2x;  g_S[5 * SEG + base] = S2y;
    g_E[0 * SEG + base] = z0x;  g_E[1 * SEG + base] = z0y;
    g_E[2 * SEG + base] = z1x;  g_E[3 * SEG + base] = z1y;
    g_E[4 * SEG + base] = z2x;  g_E[5 * SEG + base] = z2y;
    if (chunk == 0) {
        g_D0[0 * BB * 32 + b * 32 + lane] = d0x;
        g_D0[1 * BB * 32 + b * 32 + lane] = d0y;
    }
}

// ------------- Phase 2a: per-segment (P, Q, L_end) over 16 chunks -------------
__global__ __launch_bounds__(256) void ema_phase2a()
{
    const int t    = blockIdx.x * 256 + threadIdx.x;  // 0..49151
    const int lane = t & 31;
    const int u    = t >> 5;
    const int s    = u & (NSEGS - 1);
    const int b    = (u >> 2) & (BB - 1);
    const int comp = (u >> 8) & 1;
    const int a    = u >> 9;                           // 0..2

    const float bl = BL_F(a);
    const float G  = G_F(a);

    const int i0 = (a * 2 + comp) * SEG + b * NCHUNK * 32 + s * SEGLEN * 32 + lane;

    float m = 1.f, L = 0.f, Pv = 0.f, Qv = 0.f;
    #pragma unroll
    for (int k = 0; k < SEGLEN; ++k) {
        const int i = i0 + k * 32;
        const float Av = g_A[i];
        const float Sv = g_S[i];
        const float Ev = g_E[i];
        Pv += Av + 2.f * L * Sv + L * L * G;
        Qv += 2.f * m * fmaf(G, L, Sv);
        m *= bl;
        L  = fmaf(bl, L, Ev);
    }

    const int chain = (a * 2 + comp) * (BB * 32) + b * 32 + lane;
    g_P[s * NCHAIN + chain] = Pv;
    g_Q[s * NCHAIN + chain] = Qv;
    g_L[s * NCHAIN + chain] = L;
}

// ------------- Phase 2b: 4-step carry scan per chain + final reduce -------------
__global__ __launch_bounds__(256) void ema_phase2b(float* __restrict__ out)
{
    const int t    = blockIdx.x * 256 + threadIdx.x;  // 0..12287
    const int lane = t & 31;
    const int b    = (t >> 5) & (BB - 1);
    const int comp = (t >> 11) & 1;
    const int a    = t >> 12;

    const float Rc  = R_F(a);
    const float m16 = M16_F(a);
    const float Wt  = W_F(a);

    float C = g_D0[comp * BB * 32 + b * 32 + lane];

    float loss = 0.f;
    #pragma unroll
    for (int s = 0; s < NSEGS; ++s) {
        const float Pv = g_P[s * NCHAIN + t];
        const float Qv = g_Q[s * NCHAIN + t];
        const float Lv = g_L[s * NCHAIN + t];
        loss += Pv + Qv * C + Rc * C * C;
        C = fmaf(m16, C, Lv);
    }
    float v = Wt * loss;

    #pragma unroll
    for (int off = 16; off; off >>= 1)
        v += __shfl_xor_sync(0xffffffffu, v, off);
    __shared__ float sm[8];
    if (lane == 0) sm[threadIdx.x >> 5] = v;
    __syncthreads();
    if (threadIdx.x == 0) {
        float s2 = 0.f;
        #pragma unroll
        for (int i = 0; i < 8; ++i) s2 += sm[i];
        g_p2[blockIdx.x] = s2;
    }

    __threadfence();
    __syncthreads();
    __shared__ unsigned int s_isLast;
    if (threadIdx.x == 0) {
        unsigned int tk = atomicAdd(&g_count2, 1u);
        s_isLast = (tk == (unsigned int)(gridDim.x - 1));
    }
    __syncthreads();
    if (s_isLast) {
        float w = (threadIdx.x < 48) ? g_p2[threadIdx.x] : 0.f;
        #pragma unroll
        for (int off = 16; off; off >>= 1)
            w += __shfl_xor_sync(0xffffffffu, w, off);
        __shared__ float sm2[8];
        if ((threadIdx.x & 31) == 0) sm2[threadIdx.x >> 5] = w;
        __syncthreads();
        if (threadIdx.x == 0) {
            float tot = 0.f;
            #pragma unroll
            for (int i = 0; i < 8; ++i) tot += sm2[i];
            out[0] = tot * (1.0f / ((float)BB * (float)TT * (float)CC));
            g_count2 = 0;
        }
    }
}

extern "C" void kernel_launch(void* const* d_in, const int* in_sizes, int n_in,
                              void* d_out, int out_size)
{
    const float* pred = (const float*)d_in[0];
    const float* targ = (const float*)d_in[1];
    float* out = (float*)d_out;
    (void)in_sizes; (void)n_in; (void)out_size;

    ema_phase1<<<BLOCKS, THREADS>>>(pred, targ);
    ema_phase2a<<<(NSEGS * NCHAIN) / 256, 256>>>();
    ema_phase2b<<<48, 256>>>(out);
}

// round 7
// speedup vs baseline: 2.9466x; 1.1011x over previous
#include <cuda_runtime.h>

// MultiScaleTrendLoss: loss = mean_{b,t,c} sum_i w_i * ema(pred-target, a_i)[b,t,c]^2
// Exact chunked EMA: y_k = z_k + beta^{k+1} * C.
// Phase1 streams data once; A (sum z^2) is warp-reduced in-kernel (no carry
// interaction); only S, E per chunk hit memory. Phase2 (fused): per-segment
// (P,Q,L) in 4 threads/chain -> smem -> 4-step carry scan -> ticket reduce.

#define BB 64
#define TT 4096
#define CC 64
#define CHUNK 64
#define NCHUNK (TT / CHUNK)             // 64
#define NWARPS (BB * NCHUNK)            // 4096
#define THREADS 256
#define BLOCKS (NWARPS * 32 / THREADS)  // 512
#define SEG (BB * NCHUNK * 32)          // 131072 floats per (alpha,comp) plane
#define NCHAIN (3 * 2 * BB * 32)        // 12288 chains
#define NSEGS 4
#define SEGLEN (NCHUNK / NSEGS)         // 16
#define P2BLOCKS (NCHAIN * NSEGS / 256) // 192

#define AL0 0.1f
#define AL1 0.3f
#define AL2 0.5f
#define BE0 0.9f
#define BE1 0.7f
#define BE2 0.5f
#define W0f 0.5f
#define W1f 0.3f
#define W2f 0.2f

__host__ __device__ constexpr double dpow(double b, int n) {
    double r = 1.0; for (int i = 0; i < n; ++i) r *= b; return r;
}
__host__ __device__ constexpr double gsum(double beta, int L) {   // sum_{k=1..L} beta^{2k}
    double q = beta * beta; return q * (1.0 - dpow(q, L)) / (1.0 - q);
}
__host__ __device__ constexpr double geo0(double x, int n) {      // sum_{k=0..n-1} x^k
    double s = 0.0, p = 1.0; for (int k = 0; k < n; ++k) { s += p; p *= x; } return s;
}

__device__ __forceinline__ float pick3(int a, float x0, float x1, float x2) {
    return (a == 0) ? x0 : ((a == 1) ? x1 : x2);
}
#define BL_F(a)  pick3(a, (float)dpow(0.9, CHUNK), (float)dpow(0.7, CHUNK), (float)dpow(0.5, CHUNK))
#define G_F(a)   pick3(a, (float)gsum(0.9, CHUNK), (float)gsum(0.7, CHUNK), (float)gsum(0.5, CHUNK))
#define R_F(a)   pick3(a, (float)(gsum(0.9, CHUNK) * geo0(dpow(0.9, 2 * CHUNK), SEGLEN)), \
                          (float)(gsum(0.7, CHUNK) * geo0(dpow(0.7, 2 * CHUNK), SEGLEN)), \
                          (float)(gsum(0.5, CHUNK) * geo0(dpow(0.5, 2 * CHUNK), SEGLEN)))
#define M16_F(a) pick3(a, (float)dpow(0.9, CHUNK * SEGLEN), \
                          (float)dpow(0.7, CHUNK * SEGLEN), \
                          (float)dpow(0.5, CHUNK * SEGLEN))
#define W_F(a)   pick3(a, W0f, W1f, W2f)

__device__ float g_S[3 * 2 * SEG];
__device__ float g_E[3 * 2 * SEG];
__device__ float g_Apart[NWARPS];
__device__ float g_D0[2 * BB * 32];
__device__ float g_p2[P2BLOCKS];
__device__ unsigned int g_count2 = 0;

// ---------------- Phase 1: stream data once, emit per-chunk S/E + warp A-partial ----------------
__global__ __launch_bounds__(THREADS) void ema_phase1(
    const float* __restrict__ pred, const float* __restrict__ targ)
{
    const int gw   = (blockIdx.x * blockDim.x + threadIdx.x) >> 5;
    const int lane = threadIdx.x & 31;
    const int b     = gw >> 6;
    const int chunk = gw & (NCHUNK - 1);

    const float2* __restrict__ p2 = reinterpret_cast<const float2*>(pred)
                                    + (b * TT + chunk * CHUNK) * (CC / 2) + lane;
    const float2* __restrict__ q2 = reinterpret_cast<const float2*>(targ)
                                    + (b * TT + chunk * CHUNK) * (CC / 2) + lane;

    constexpr int P = 4;
    float2 bp[P], bq[P];
    #pragma unroll
    for (int i = 0; i < P; ++i) { bp[i] = p2[i * (CC / 2)]; bq[i] = q2[i * (CC / 2)]; }

    float z0x = 0.f, z0y = 0.f, z1x = 0.f, z1y = 0.f, z2x = 0.f, z2y = 0.f;
    float A0x = 0.f, A0y = 0.f, A1x = 0.f, A1y = 0.f, A2x = 0.f, A2y = 0.f;
    float S0x = 0.f, S0y = 0.f, S1x = 0.f, S1y = 0.f, S2x = 0.f, S2y = 0.f;
    float pw0 = BE0, pw1 = BE1, pw2 = BE2;

    const float d0x = bp[0].x - bq[0].x;
    const float d0y = bp[0].y - bq[0].y;

    auto step = [&](float dx, float dy) {
        z0x = fmaf(AL0, dx - z0x, z0x);  z0y = fmaf(AL0, dy - z0y, z0y);
        z1x = fmaf(AL1, dx - z1x, z1x);  z1y = fmaf(AL1, dy - z1y, z1y);
        z2x = fmaf(AL2, dx - z2x, z2x);  z2y = fmaf(AL2, dy - z2y, z2y);
        A0x = fmaf(z0x, z0x, A0x);  A0y = fmaf(z0y, z0y, A0y);
        A1x = fmaf(z1x, z1x, A1x);  A1y = fmaf(z1y, z1y, A1y);
        A2x = fmaf(z2x, z2x, A2x);  A2y = fmaf(z2y, z2y, A2y);
        S0x = fmaf(pw0, z0x, S0x);  S0y = fmaf(pw0, z0y, S0y);
        S1x = fmaf(pw1, z1x, S1x);  S1y = fmaf(pw1, z1y, S1y);
        S2x = fmaf(pw2, z2x, S2x);  S2y = fmaf(pw2, z2y, S2y);
        pw0 *= BE0; pw1 *= BE1; pw2 *= BE2;
    };

    #pragma unroll 8
    for (int k = 0; k < CHUNK - P; ++k) {
        const int slot = k & (P - 1);
        const float dx = bp[slot].x - bq[slot].x;
        const float dy = bp[slot].y - bq[slot].y;
        bp[slot] = p2[(k + P) * (CC / 2)];
        bq[slot] = q2[(k + P) * (CC / 2)];
        step(dx, dy);
    }
    #pragma unroll
    for (int k = CHUNK - P; k < CHUNK; ++k) {
        const int slot = k & (P - 1);
        step(bp[slot].x - bq[slot].x, bp[slot].y - bq[slot].y);
    }

    const int base = (b * NCHUNK + chunk) * 32 + lane;
    g_S[0 * SEG + base] = S0x;  g_S[1 * SEG + base] = S0y;
    g_S[2 * SEG + base] = S1x;  g_S[3 * SEG + base] = S1y;
    g_S[4 * SEG + base] = S2x;  g_S[5 * SEG + base] = S2y;
    g_E[0 * SEG + base] = z0x;  g_E[1 * SEG + base] = z0y;
    g_E[2 * SEG + base] = z1x;  g_E[3 * SEG + base] = z1y;
    g_E[4 * SEG + base] = z2x;  g_E[5 * SEG + base] = z2y;
    if (chunk == 0) {
        g_D0[0 * BB * 32 + b * 32 + lane] = d0x;
        g_D0[1 * BB * 32 + b * 32 + lane] = d0y;
    }

    // weighted A contribution: no carry interaction -> reduce to 1 scalar/warp
    float ap = W0f * (A0x + A0y) + W1f * (A1x + A1y) + W2f * (A2x + A2y);
    #pragma unroll
    for (int off = 16; off; off >>= 1)
        ap += __shfl_xor_sync(0xffffffffu, ap, off);
    if (lane == 0) g_Apart[gw] = ap;
}

// ------- Phase 2 (fused): segment (P,Q,L) -> smem -> carry scan -> ticket reduce -------
__global__ __launch_bounds__(256) void ema_phase2(float* __restrict__ out)
{
    const int tid = threadIdx.x;
    const int s   = tid & (NSEGS - 1);           // segment 0..3
    const int cl  = tid >> 2;                    // chain-local 0..63
    const int chain = blockIdx.x * 64 + cl;
    const int lane_c = chain & 31;
    const int b      = (chain >> 5) & (BB - 1);
    const int comp   = (chain >> 11) & 1;
    const int a      = chain >> 12;

    const float bl = BL_F(a);
    const float G  = G_F(a);

    const int i0 = (a * 2 + comp) * SEG + b * NCHUNK * 32 + s * SEGLEN * 32 + lane_c;

    float m = 1.f, L = 0.f, Pv = 0.f, Qv = 0.f;
    #pragma unroll
    for (int k = 0; k < SEGLEN; ++k) {
        const int i = i0 + k * 32;
        const float Sv = g_S[i];
        const float Ev = g_E[i];
        Pv += 2.f * L * Sv + L * L * G;
        Qv += 2.f * m * fmaf(G, L, Sv);
        m *= bl;
        L  = fmaf(bl, L, Ev);
    }

    __shared__ float sP[256], sQ[256], sL[256];
    sP[tid] = Pv; sQ[tid] = Qv; sL[tid] = L;
    __syncthreads();

    float v = 0.f;
    if (tid < 64) {
        const int ch2    = blockIdx.x * 64 + tid;
        const int lane2  = ch2 & 31;
        const int b2     = (ch2 >> 5) & (BB - 1);
        const int comp2  = (ch2 >> 11) & 1;
        const int a2     = ch2 >> 12;
        const float Rc   = R_F(a2);
        const float m16  = M16_F(a2);
        const float Wt   = W_F(a2);

        float C = g_D0[comp2 * BB * 32 + b2 * 32 + lane2];
        float loss = 0.f;
        #pragma unroll
        for (int ss = 0; ss < NSEGS; ++ss) {
            const int j = tid * NSEGS + ss;
            loss += sP[j] + sQ[j] * C + Rc * C * C;
            C = fmaf(m16, C, sL[j]);
        }
        v = Wt * loss;
        #pragma unroll
        for (int off = 16; off; off >>= 1)
            v += __shfl_xor_sync(0xffffffffu, v, off);
    }
    __shared__ float sblk[2];
    if (tid == 0)  sblk[0] = v;
    if (tid == 32) sblk[1] = v;
    __syncthreads();
    if (tid == 0) g_p2[blockIdx.x] = sblk[0] + sblk[1];

    // deterministic last-block final reduce (cross terms + A partials)
    __threadfence();
    __syncthreads();
    __shared__ unsigned int s_isLast;
    if (tid == 0) {
        unsigned int tk = atomicAdd(&g_count2, 1u);
        s_isLast = (tk == (unsigned int)(gridDim.x - 1));
    }
    __syncthreads();
    if (s_isLast) {
        float w = 0.f;
        for (int i = tid; i < P2BLOCKS; i += 256) w += g_p2[i];
        #pragma unroll
        for (int i = tid; i < NWARPS; i += 256) w += g_Apart[i];
        #pragma unroll
        for (int off = 16; off; off >>= 1)
            w += __shfl_xor_sync(0xffffffffu, w, off);
        __shared__ float sm2[8];
        if ((tid & 31) == 0) sm2[tid >> 5] = w;
        __syncthreads();
        if (tid == 0) {
            float tot = 0.f;
            #pragma unroll
            for (int i = 0; i < 8; ++i) tot += sm2[i];
            out[0] = tot * (1.0f / ((float)BB * (float)TT * (float)CC));
            g_count2 = 0;
        }
    }
}

extern "C" void kernel_launch(void* const* d_in, const int* in_sizes, int n_in,
                              void* d_out, int out_size)
{
    const float* pred = (const float*)d_in[0];
    const float* targ = (const float*)d_in[1];
    float* out = (float*)d_out;
    (void)in_sizes; (void)n_in; (void)out_size;

    ema_phase1<<<BLOCKS, THREADS>>>(pred, targ);
    ema_phase2<<<P2BLOCKS, 256>>>(out);
}

// round 8
// speedup vs baseline: 2.9494x; 1.0010x over previous
#include <cuda_runtime.h>

// MultiScaleTrendLoss: loss = mean_{b,t,c} sum_i w_i * ema(pred-target, a_i)[b,t,c]^2
// Exact chunked EMA: y_k = z_k + beta^{k+1} * C.
// Single fused kernel: Phase A streams data once (S/E per chunk to global, A
// warp-reduced in smem). In-kernel grid barrier (all 512 blocks co-resident by
// __launch_bounds__(256,4)). Phase B: all blocks compute per-segment (P,Q,L)
// from L2-hot S/E, scan carries per chain, deterministic ticket final reduce.

#define BB 64
#define TT 4096
#define CC 64
#define CHUNK 64
#define NCHUNK (TT / CHUNK)             // 64
#define NWARPS (BB * NCHUNK)            // 4096
#define THREADS 256
#define GRID (NWARPS * 32 / THREADS)    // 512
#define SEG (BB * NCHUNK * 32)          // 131072 floats per (alpha,comp) plane
#define NCHAIN (3 * 2 * BB * 32)        // 12288 chains
#define NSEGS 8
#define SEGLEN (NCHUNK / NSEGS)         // 8
#define CH_PER_BLK (NCHAIN / GRID)      // 24 chains per block
#define UNITS_PER_BLK (CH_PER_BLK * NSEGS) // 192

#define AL0 0.1f
#define AL1 0.3f
#define AL2 0.5f
#define BE0 0.9f
#define BE1 0.7f
#define BE2 0.5f
#define W0f 0.5f
#define W1f 0.3f
#define W2f 0.2f

__host__ __device__ constexpr double dpow(double b, int n) {
    double r = 1.0; for (int i = 0; i < n; ++i) r *= b; return r;
}
__host__ __device__ constexpr double gsum(double beta, int L) {   // sum_{k=1..L} beta^{2k}
    double q = beta * beta; return q * (1.0 - dpow(q, L)) / (1.0 - q);
}
__host__ __device__ constexpr double geo0(double x, int n) {      // sum_{k=0..n-1} x^k
    double s = 0.0, p = 1.0; for (int k = 0; k < n; ++k) { s += p; p *= x; } return s;
}

__device__ __forceinline__ float pick3(int a, float x0, float x1, float x2) {
    return (a == 0) ? x0 : ((a == 1) ? x1 : x2);
}
#define BL_F(a)  pick3(a, (float)dpow(0.9, CHUNK), (float)dpow(0.7, CHUNK), (float)dpow(0.5, CHUNK))
#define G_F(a)   pick3(a, (float)gsum(0.9, CHUNK), (float)gsum(0.7, CHUNK), (float)gsum(0.5, CHUNK))
#define R8_F(a)  pick3(a, (float)(gsum(0.9, CHUNK) * geo0(dpow(0.9, 2 * CHUNK), SEGLEN)), \
                          (float)(gsum(0.7, CHUNK) * geo0(dpow(0.7, 2 * CHUNK), SEGLEN)), \
                          (float)(gsum(0.5, CHUNK) * geo0(dpow(0.5, 2 * CHUNK), SEGLEN)))
#define M8_F(a)  pick3(a, (float)dpow(0.9, CHUNK * SEGLEN), \
                          (float)dpow(0.7, CHUNK * SEGLEN), \
                          (float)dpow(0.5, CHUNK * SEGLEN))
#define W_F(a)   pick3(a, W0f, W1f, W2f)

__device__ float g_S[3 * 2 * SEG];
__device__ float g_E[3 * 2 * SEG];
__device__ float g_D0[2 * BB * 32];
__device__ float g_p2[GRID];
__device__ unsigned int g_bar  = 0;
__device__ unsigned int g_tick = 0;

__global__ __launch_bounds__(THREADS, 4) void ema_fused(
    const float* __restrict__ pred, const float* __restrict__ targ,
    float* __restrict__ out)
{
    const int tid  = threadIdx.x;
    const int gw   = (blockIdx.x * THREADS + tid) >> 5;
    const int lane = tid & 31;
    const int wrp  = tid >> 5;

    __shared__ float sA[8];
    __shared__ float sP[UNITS_PER_BLK], sQ[UNITS_PER_BLK], sL[UNITS_PER_BLK];

    // ================= Phase A: stream data once =================
    {
        const int b     = gw >> 6;
        const int chunk = gw & (NCHUNK - 1);

        const float2* __restrict__ p2 = reinterpret_cast<const float2*>(pred)
                                        + (b * TT + chunk * CHUNK) * (CC / 2) + lane;
        const float2* __restrict__ q2 = reinterpret_cast<const float2*>(targ)
                                        + (b * TT + chunk * CHUNK) * (CC / 2) + lane;

        constexpr int P = 4;
        float2 bp[P], bq[P];
        #pragma unroll
        for (int i = 0; i < P; ++i) { bp[i] = p2[i * (CC / 2)]; bq[i] = q2[i * (CC / 2)]; }

        float z0x = 0.f, z0y = 0.f, z1x = 0.f, z1y = 0.f, z2x = 0.f, z2y = 0.f;
        float A0x = 0.f, A0y = 0.f, A1x = 0.f, A1y = 0.f, A2x = 0.f, A2y = 0.f;
        float S0x = 0.f, S0y = 0.f, S1x = 0.f, S1y = 0.f, S2x = 0.f, S2y = 0.f;
        float pw0 = BE0, pw1 = BE1, pw2 = BE2;

        const float d0x = bp[0].x - bq[0].x;
        const float d0y = bp[0].y - bq[0].y;

        auto step = [&](float dx, float dy) {
            z0x = fmaf(AL0, dx - z0x, z0x);  z0y = fmaf(AL0, dy - z0y, z0y);
            z1x = fmaf(AL1, dx - z1x, z1x);  z1y = fmaf(AL1, dy - z1y, z1y);
            z2x = fmaf(AL2, dx - z2x, z2x);  z2y = fmaf(AL2, dy - z2y, z2y);
            A0x = fmaf(z0x, z0x, A0x);  A0y = fmaf(z0y, z0y, A0y);
            A1x = fmaf(z1x, z1x, A1x);  A1y = fmaf(z1y, z1y, A1y);
            A2x = fmaf(z2x, z2x, A2x);  A2y = fmaf(z2y, z2y, A2y);
            S0x = fmaf(pw0, z0x, S0x);  S0y = fmaf(pw0, z0y, S0y);
            S1x = fmaf(pw1, z1x, S1x);  S1y = fmaf(pw1, z1y, S1y);
            S2x = fmaf(pw2, z2x, S2x);  S2y = fmaf(pw2, z2y, S2y);
            pw0 *= BE0; pw1 *= BE1; pw2 *= BE2;
        };

        #pragma unroll 8
        for (int k = 0; k < CHUNK - P; ++k) {
            const int slot = k & (P - 1);
            const float dx = bp[slot].x - bq[slot].x;
            const float dy = bp[slot].y - bq[slot].y;
            bp[slot] = p2[(k + P) * (CC / 2)];
            bq[slot] = q2[(k + P) * (CC / 2)];
            step(dx, dy);
        }
        #pragma unroll
        for (int k = CHUNK - P; k < CHUNK; ++k) {
            const int slot = k & (P - 1);
            step(bp[slot].x - bq[slot].x, bp[slot].y - bq[slot].y);
        }

        const int base = (b * NCHUNK + chunk) * 32 + lane;
        g_S[0 * SEG + base] = S0x;  g_S[1 * SEG + base] = S0y;
        g_S[2 * SEG + base] = S1x;  g_S[3 * SEG + base] = S1y;
        g_S[4 * SEG + base] = S2x;  g_S[5 * SEG + base] = S2y;
        g_E[0 * SEG + base] = z0x;  g_E[1 * SEG + base] = z0y;
        g_E[2 * SEG + base] = z1x;  g_E[3 * SEG + base] = z1y;
        g_E[4 * SEG + base] = z2x;  g_E[5 * SEG + base] = z2y;
        if (chunk == 0) {
            g_D0[0 * BB * 32 + b * 32 + lane] = d0x;
            g_D0[1 * BB * 32 + b * 32 + lane] = d0y;
        }

        // weighted A contribution (no carry interaction): warp-reduce to smem
        float ap = W0f * (A0x + A0y) + W1f * (A1x + A1y) + W2f * (A2x + A2y);
        #pragma unroll
        for (int off = 16; off; off >>= 1)
            ap += __shfl_xor_sync(0xffffffffu, ap, off);
        if (lane == 0) sA[wrp] = ap;
    }

    // ================= Grid barrier (all GRID blocks co-resident) =================
    __syncthreads();
    if (tid == 0) {
        __threadfence();                       // release S/E/D0 stores
        atomicAdd(&g_bar, 1u);
        volatile unsigned int* vb = &g_bar;
        while (*vb < (unsigned int)GRID) { __nanosleep(64); }
    }
    __syncthreads();
    __threadfence();                           // acquire other blocks' stores

    // ================= Phase B: per-segment (P,Q,L), scan, reduce =================
    if (tid < UNITS_PER_BLK) {
        const int s  = tid & (NSEGS - 1);              // segment 0..7
        const int cl = tid >> 3;                       // chain-local 0..23
        const int chain  = blockIdx.x * CH_PER_BLK + cl;
        const int lane_c = chain & 31;
        const int b      = (chain >> 5) & (BB - 1);
        const int comp   = (chain >> 11) & 1;
        const int a      = chain >> 12;

        const float bl = BL_F(a);
        const float G  = G_F(a);

        const int i0 = (a * 2 + comp) * SEG + b * NCHUNK * 32 + s * SEGLEN * 32 + lane_c;

        float m = 1.f, L = 0.f, Pv = 0.f, Qv = 0.f;
        #pragma unroll
        for (int k = 0; k < SEGLEN; ++k) {
            const int i = i0 + k * 32;
            const float Sv = g_S[i];
            const float Ev = g_E[i];
            Pv += 2.f * L * Sv + L * L * G;
            Qv += 2.f * m * fmaf(G, L, Sv);
            m *= bl;
            L  = fmaf(bl, L, Ev);
        }
        sP[tid] = Pv; sQ[tid] = Qv; sL[tid] = L;
    }
    __syncthreads();

    if (tid < 32) {                                     // warp 0 scans 24 chains
        float v = 0.f;
        if (tid < CH_PER_BLK) {
            const int chain  = blockIdx.x * CH_PER_BLK + tid;
            const int lane_c = chain & 31;
            const int b      = (chain >> 5) & (BB - 1);
            const int comp   = (chain >> 11) & 1;
            const int a      = chain >> 12;
            const float Rc  = R8_F(a);
            const float m8  = M8_F(a);
            const float Wt  = W_F(a);

            float C = g_D0[comp * BB * 32 + b * 32 + lane_c];
            float loss = 0.f;
            #pragma unroll
            for (int ss = 0; ss < NSEGS; ++ss) {
                const int j = tid * NSEGS + ss;
                loss += sP[j] + sQ[j] * C + Rc * C * C;
                C = fmaf(m8, C, sL[j]);
            }
            v = Wt * loss;
        }
        #pragma unroll
        for (int off = 16; off; off >>= 1)
            v += __shfl_xor_sync(0xffffffffu, v, off);
        if (tid == 0) {
            float apb = 0.f;
            #pragma unroll
            for (int i = 0; i < 8; ++i) apb += sA[i];
            g_p2[blockIdx.x] = v + apb;
        }
    }

    // ================= Deterministic final ticket reduce =================
    __threadfence();
    __syncthreads();
    __shared__ unsigned int s_isLast;
    if (tid == 0) {
        unsigned int tk = atomicAdd(&g_tick, 1u);
        s_isLast = (tk == (unsigned int)(GRID - 1));
    }
    __syncthreads();
    if (s_isLast) {
        float w = 0.f;
        #pragma unroll
        for (int i = tid; i < GRID; i += THREADS) w += g_p2[i];
        #pragma unroll
        for (int off = 16; off; off >>= 1)
            w += __shfl_xor_sync(0xffffffffu, w, off);
        __shared__ float sm2[8];
        if ((tid & 31) == 0) sm2[tid >> 5] = w;
        __syncthreads();
        if (tid == 0) {
            float tot = 0.f;
            #pragma unroll
            for (int i = 0; i < 8; ++i) tot += sm2[i];
            out[0] = tot * (1.0f / ((float)BB * (float)TT * (float)CC));
            g_tick = 0;                     // reset for next graph replay
            g_bar  = 0;
        }
    }
}

extern "C" void kernel_launch(void* const* d_in, const int* in_sizes, int n_in,
                              void* d_out, int out_size)
{
    const float* pred = (const float*)d_in[0];
    const float* targ = (const float*)d_in[1];
    float* out = (float*)d_out;
    (void)in_sizes; (void)n_in; (void)out_size;

    ema_fused<<<GRID, THREADS>>>(pred, targ, out);
}